// round 2
// baseline (speedup 1.0000x reference)
#include <cuda_runtime.h>
#include <cuda_bf16.h>

// Problem constants
#define NN   10000
#define EE   30000
#define D_IN 64
#define E_DIM 16
#define H1   128
#define H2   64
#define CC   10
#define KX   17            // E_DIM + 1 bias slot
#define Q1W  (KX*H2)       // 1088
#define Q2W  (KX*CC)       // 170

// ---------------- device scratch (no allocations allowed) ----------------
__device__ float g_h1[NN*H1];       // relu(x@W1+b1)
__device__ float g_q1[NN*Q1W];      // node-factorized layer-1 tensor  (43.5 MB)
__device__ float g_agg1[NN*H2];     // root1 term + scatter-add
__device__ float g_h2[NN*H2];       // relu(agg1)
__device__ float g_q2[NN*Q2W];      // node-factorized layer-2 tensor
__device__ float g_agg2[NN*CC];     // root2 term + scatter-add
__device__ float g_M1[H1*Q1W];      // packed [i][k*64+o] = We1[k][i*64+o] (k<16) / be1[i*64+o] (k=16)
__device__ float g_M2[H2*Q2W];      // packed [j][k*10+c]

// ---------------- pack kernels ----------------
__global__ void pack_m1(const float* __restrict__ We1, const float* __restrict__ be1) {
    int idx = blockIdx.x * blockDim.x + threadIdx.x;
    if (idx >= H1 * Q1W) return;
    int i = idx / Q1W;
    int col = idx - i * Q1W;
    int k = col / H2;
    int o = col - k * H2;
    g_M1[idx] = (k < E_DIM) ? We1[k * (H1 * H2) + i * H2 + o] : be1[i * H2 + o];
}

__global__ void pack_m2(const float* __restrict__ We2, const float* __restrict__ be2) {
    int idx = blockIdx.x * blockDim.x + threadIdx.x;
    if (idx >= H2 * Q2W) return;
    int j = idx / Q2W;
    int col = idx - j * Q2W;
    int k = col / CC;
    int c = col - k * CC;
    g_M2[idx] = (k < E_DIM) ? We2[k * (H2 * CC) + j * CC + c] : be2[j * CC + c];
}

// ---------------- generic register-tiled SGEMM ----------------
// C[M,N] = A[M,K] @ B[K,N] (+bias)(+relu).  BM=BN=64, BK=16, 16x16 threads, 4x4 per thread.
#define BM 64
#define BN 64
#define BK 16
__global__ __launch_bounds__(256) void sgemm(
    const float* __restrict__ A, const float* __restrict__ B, float* __restrict__ C,
    int M, int N, int K, const float* __restrict__ bias, int do_relu)
{
    __shared__ float As[BK][BM + 1];
    __shared__ float Bs[BK][BN];

    int tid = threadIdx.x;
    int tx = tid & 15;       // 0..15 -> N direction
    int ty = tid >> 4;       // 0..15 -> M direction
    int bm0 = blockIdx.y * BM;
    int bn0 = blockIdx.x * BN;

    float acc[4][4];
    #pragma unroll
    for (int i = 0; i < 4; i++)
        #pragma unroll
        for (int j = 0; j < 4; j++) acc[i][j] = 0.f;

    for (int k0 = 0; k0 < K; k0 += BK) {
        // load A tile: 64x16, coalesced along K, stored transposed As[k][m]
        #pragma unroll
        for (int l = 0; l < 4; l++) {
            int idx = tid + l * 256;          // 0..1023
            int m = idx >> 4;                 // /16
            int k = idx & 15;
            int gm = bm0 + m, gk = k0 + k;
            As[k][m] = (gm < M && gk < K) ? A[(size_t)gm * K + gk] : 0.f;
        }
        // load B tile: 16x64, coalesced along N
        #pragma unroll
        for (int l = 0; l < 4; l++) {
            int idx = tid + l * 256;
            int k = idx >> 6;                 // /64
            int n = idx & 63;
            int gk = k0 + k, gn = bn0 + n;
            Bs[k][n] = (gk < K && gn < N) ? B[(size_t)gk * N + gn] : 0.f;
        }
        __syncthreads();

        #pragma unroll
        for (int k = 0; k < BK; k++) {
            float ra[4], rb[4];
            #pragma unroll
            for (int i = 0; i < 4; i++) ra[i] = As[k][ty * 4 + i];
            #pragma unroll
            for (int j = 0; j < 4; j++) rb[j] = Bs[k][tx * 4 + j];
            #pragma unroll
            for (int i = 0; i < 4; i++)
                #pragma unroll
                for (int j = 0; j < 4; j++) acc[i][j] = fmaf(ra[i], rb[j], acc[i][j]);
        }
        __syncthreads();
    }

    #pragma unroll
    for (int i = 0; i < 4; i++) {
        int gm = bm0 + ty * 4 + i;
        if (gm >= M) continue;
        #pragma unroll
        for (int j = 0; j < 4; j++) {
            int gn = bn0 + tx * 4 + j;
            if (gn >= N) continue;
            float v = acc[i][j];
            if (bias) v += bias[gn];
            if (do_relu) v = fmaxf(v, 0.f);
            C[(size_t)gm * N + gn] = v;
        }
    }
}

// ---------------- edge kernels (warp per edge) ----------------
// edge_index is int32 on the device side (harness converts int64 -> int32).
__global__ void edge_l1(const float* __restrict__ ea, const int* __restrict__ ei, int E) {
    int e = blockIdx.x * (blockDim.x >> 5) + (threadIdx.x >> 5);
    if (e >= E) return;
    int lane = threadIdx.x & 31;
    float cv = (lane < E_DIM) ? ea[(size_t)e * E_DIM + lane] : (lane == E_DIM ? 1.f : 0.f);
    int src = ei[e];
    int dst = ei[E + e];
    if ((unsigned)src >= NN || (unsigned)dst >= NN) return;  // defensive: bad index -> skip, not crash
    const float* q = g_q1 + (size_t)src * Q1W;
    float a0 = 0.f, a1 = 0.f;
    #pragma unroll
    for (int k = 0; k < KX; k++) {
        float ck = __shfl_sync(0xffffffffu, cv, k);
        a0 = fmaf(ck, q[k * H2 + lane], a0);
        a1 = fmaf(ck, q[k * H2 + lane + 32], a1);
    }
    atomicAdd(&g_agg1[(size_t)dst * H2 + lane], a0);
    atomicAdd(&g_agg1[(size_t)dst * H2 + lane + 32], a1);
}

__global__ void edge_l2(const float* __restrict__ ea, const int* __restrict__ ei, int E) {
    int e = blockIdx.x * (blockDim.x >> 5) + (threadIdx.x >> 5);
    if (e >= E) return;
    int lane = threadIdx.x & 31;
    float cv = (lane < E_DIM) ? ea[(size_t)e * E_DIM + lane] : (lane == E_DIM ? 1.f : 0.f);
    int src = ei[e];
    int dst = ei[E + e];
    if ((unsigned)src >= NN || (unsigned)dst >= NN) return;
    const float* q = g_q2 + (size_t)src * Q2W;
    float a = 0.f;
    #pragma unroll
    for (int k = 0; k < KX; k++) {
        float ck = __shfl_sync(0xffffffffu, cv, k);
        if (lane < CC) a = fmaf(ck, q[k * CC + lane], a);
    }
    if (lane < CC) atomicAdd(&g_agg2[(size_t)dst * CC + lane], a);
}

// ---------------- relu + log_softmax ----------------
__global__ void relu_copy(int n) {
    int i = blockIdx.x * blockDim.x + threadIdx.x;
    if (i < n) g_h2[i] = fmaxf(g_agg1[i], 0.f);
}

__global__ void log_softmax_rows(float* __restrict__ out, int n) {
    int r = blockIdx.x * blockDim.x + threadIdx.x;
    if (r >= n) return;
    const float* z = g_agg2 + (size_t)r * CC;
    float m = z[0];
    #pragma unroll
    for (int c = 1; c < CC; c++) m = fmaxf(m, z[c]);
    float s = 0.f;
    #pragma unroll
    for (int c = 0; c < CC; c++) s += __expf(z[c] - m);
    float ls = m + logf(s);
    #pragma unroll
    for (int c = 0; c < CC; c++) out[(size_t)r * CC + c] = z[c] - ls;
}

// ---------------- launch ----------------
extern "C" void kernel_launch(void* const* d_in, const int* in_sizes, int n_in,
                              void* d_out, int out_size)
{
    const float* x     = (const float*)d_in[0];
    const float* ea    = (const float*)d_in[1];
    const int*   ei    = (const int*)d_in[2];     // int64 in reference -> int32 on device
    const float* W1    = (const float*)d_in[3];
    const float* b1    = (const float*)d_in[4];
    const float* We1   = (const float*)d_in[5];
    const float* be1   = (const float*)d_in[6];
    const float* root1 = (const float*)d_in[7];
    const float* bias1 = (const float*)d_in[8];
    const float* We2   = (const float*)d_in[9];
    const float* be2   = (const float*)d_in[10];
    const float* root2 = (const float*)d_in[11];
    const float* bias2 = (const float*)d_in[12];
    float* out = (float*)d_out;

    int N = in_sizes[0] / D_IN;        // 10000
    int E = in_sizes[2] / 2;           // 30000

    float *p_h1, *p_q1, *p_agg1, *p_h2, *p_q2, *p_M1, *p_M2, *p_agg2;
    cudaGetSymbolAddress((void**)&p_h1,   g_h1);
    cudaGetSymbolAddress((void**)&p_q1,   g_q1);
    cudaGetSymbolAddress((void**)&p_agg1, g_agg1);
    cudaGetSymbolAddress((void**)&p_h2,   g_h2);
    cudaGetSymbolAddress((void**)&p_q2,   g_q2);
    cudaGetSymbolAddress((void**)&p_M1,   g_M1);
    cudaGetSymbolAddress((void**)&p_M2,   g_M2);
    cudaGetSymbolAddress((void**)&p_agg2, g_agg2);

    dim3 blk(256);

    // pack edge-MLP weight matrices into node-GEMM operands
    pack_m1<<<(H1 * Q1W + 255) / 256, blk>>>(We1, be1);
    pack_m2<<<(H2 * Q2W + 255) / 256, blk>>>(We2, be2);

    // h1 = relu(x @ W1 + b1)            [N,64]@[64,128]
    {
        dim3 g((H1 + BN - 1) / BN, (N + BM - 1) / BM);
        sgemm<<<g, blk>>>(x, W1, p_h1, N, H1, D_IN, b1, 1);
    }
    // q1 = h1 @ M1                      [N,128]@[128,1088]   (dominant GEMM)
    {
        dim3 g((Q1W + BN - 1) / BN, (N + BM - 1) / BM);
        sgemm<<<g, blk>>>(p_h1, p_M1, p_q1, N, Q1W, H1, nullptr, 0);
    }
    // agg1 = h1 @ root1 + bias1         [N,128]@[128,64]  (pre-seed for scatter)
    {
        dim3 g((H2 + BN - 1) / BN, (N + BM - 1) / BM);
        sgemm<<<g, blk>>>(p_h1, root1, p_agg1, N, H2, H1, bias1, 0);
    }
    // edge scatter layer 1
    edge_l1<<<(E + 3) / 4, 128>>>(ea, ei, E);
    // h2 = relu(agg1)
    relu_copy<<<(N * H2 + 255) / 256, blk>>>(N * H2);
    // q2 = h2 @ M2                      [N,64]@[64,170]
    {
        dim3 g((Q2W + BN - 1) / BN, (N + BM - 1) / BM);
        sgemm<<<g, blk>>>(p_h2, p_M2, p_q2, N, Q2W, H2, nullptr, 0);
    }
    // agg2 = h2 @ root2 + bias2         [N,64]@[64,10]
    {
        dim3 g((CC + BN - 1) / BN, (N + BM - 1) / BM);
        sgemm<<<g, blk>>>(p_h2, root2, p_agg2, N, CC, H2, bias2, 0);
    }
    // edge scatter layer 2
    edge_l2<<<(E + 3) / 4, 128>>>(ea, ei, E);
    // log_softmax rows -> out
    log_softmax_rows<<<(N + 255) / 256, blk>>>(out, N);
}

// round 3
// speedup vs baseline: 1.7235x; 1.7235x over previous
#include <cuda_runtime.h>
#include <cuda_bf16.h>

// Problem constants
#define NN   10000
#define EE   30000
#define D_IN 64
#define E_DIM 16
#define H1   128
#define H2   64
#define CC   10
#define KX   17            // E_DIM + 1 bias slot
#define Q1W  (KX*H2)       // 1088
#define Q2W  (KX*CC)       // 170

// ---------------- device scratch ----------------
__device__ float g_h1[NN*H1];
__device__ float g_q1[NN*Q1W];
__device__ float g_agg1[NN*H2];
__device__ float g_h2[NN*H2];
__device__ float g_q2[NN*Q2W];
__device__ float g_agg2[NN*CC];
__device__ float g_M1[H1*Q1W];
__device__ float g_M2[H2*Q2W];

// ---------------- pack kernels ----------------
__global__ void pack_m1(const float* __restrict__ We1, const float* __restrict__ be1) {
    int idx = blockIdx.x * blockDim.x + threadIdx.x;
    if (idx >= H1 * Q1W) return;
    int i = idx / Q1W;
    int col = idx - i * Q1W;
    int k = col / H2;
    int o = col - k * H2;
    g_M1[idx] = (k < E_DIM) ? We1[k * (H1 * H2) + i * H2 + o] : be1[i * H2 + o];
}

__global__ void pack_m2(const float* __restrict__ We2, const float* __restrict__ be2) {
    int idx = blockIdx.x * blockDim.x + threadIdx.x;
    if (idx >= H2 * Q2W) return;
    int j = idx / Q2W;
    int col = idx - j * Q2W;
    int k = col / CC;
    int c = col - k * CC;
    g_M2[idx] = (k < E_DIM) ? We2[k * (H2 * CC) + j * CC + c] : be2[j * CC + c];
}

// ================= high-intensity SGEMM: 128x128 tile, BK=8, 8x8/thread =================
// Requires: K % 8 == 0, N % 4 == 0. M,N ragged edges handled by guards.
#define GM 128
#define GN 128
#define GK 8
__global__ __launch_bounds__(256) void sgemm128(
    const float* __restrict__ A, const float* __restrict__ B, float* __restrict__ C,
    int M, int N, int K, const float* __restrict__ bias, int do_relu)
{
    __shared__ float As[GK][GM];   // [k][m]
    __shared__ float Bs[GK][GN];   // [k][n]

    int tid = threadIdx.x;
    int tx = tid & 15;             // N-dir, 16 threads
    int ty = tid >> 4;             // M-dir, 16 threads
    int bm0 = blockIdx.y * GM;
    int bn0 = blockIdx.x * GN;

    float acc[8][8];
    #pragma unroll
    for (int i = 0; i < 8; i++)
        #pragma unroll
        for (int j = 0; j < 8; j++) acc[i][j] = 0.f;

    for (int k0 = 0; k0 < K; k0 += GK) {
        // A tile: 128 rows x 8 k; one float4 per thread (K%8==0 so in-bounds along K)
        {
            int row = tid >> 1;
            int kq  = (tid & 1) * 4;
            int gm  = bm0 + row;
            float4 v = make_float4(0.f, 0.f, 0.f, 0.f);
            if (gm < M) v = *(const float4*)(A + (size_t)gm * K + k0 + kq);
            As[kq + 0][row] = v.x;
            As[kq + 1][row] = v.y;
            As[kq + 2][row] = v.z;
            As[kq + 3][row] = v.w;
        }
        // B tile: 8 rows x 128 cols; one float4 per thread (N%4==0 so gn<N => gn+3<N)
        {
            int krow = tid >> 5;
            int col  = (tid & 31) * 4;
            int gn   = bn0 + col;
            float4 v = make_float4(0.f, 0.f, 0.f, 0.f);
            if (gn < N) v = *(const float4*)(B + (size_t)(k0 + krow) * N + gn);
            *(float4*)&Bs[krow][col] = v;
        }
        __syncthreads();

        #pragma unroll
        for (int k = 0; k < GK; k++) {
            float ra[8], rb[8];
            *(float4*)&ra[0] = *(const float4*)&As[k][ty * 4];
            *(float4*)&ra[4] = *(const float4*)&As[k][ty * 4 + 64];
            *(float4*)&rb[0] = *(const float4*)&Bs[k][tx * 4];
            *(float4*)&rb[4] = *(const float4*)&Bs[k][tx * 4 + 64];
            #pragma unroll
            for (int i = 0; i < 8; i++)
                #pragma unroll
                for (int j = 0; j < 8; j++)
                    acc[i][j] = fmaf(ra[i], rb[j], acc[i][j]);
        }
        __syncthreads();
    }

    // store: rows {ty*4+i, ty*4+64+i}, cols {tx*4.., tx*4+64..}, float4 (N%4==0)
    #pragma unroll
    for (int ih = 0; ih < 2; ih++) {
        #pragma unroll
        for (int i = 0; i < 4; i++) {
            int gm = bm0 + ty * 4 + ih * 64 + i;
            if (gm >= M) continue;
            #pragma unroll
            for (int jh = 0; jh < 2; jh++) {
                int gn = bn0 + tx * 4 + jh * 64;
                if (gn >= N) continue;
                float4 v;
                v.x = acc[ih * 4 + i][jh * 4 + 0];
                v.y = acc[ih * 4 + i][jh * 4 + 1];
                v.z = acc[ih * 4 + i][jh * 4 + 2];
                v.w = acc[ih * 4 + i][jh * 4 + 3];
                if (bias) {
                    v.x += bias[gn + 0]; v.y += bias[gn + 1];
                    v.z += bias[gn + 2]; v.w += bias[gn + 3];
                }
                if (do_relu) {
                    v.x = fmaxf(v.x, 0.f); v.y = fmaxf(v.y, 0.f);
                    v.z = fmaxf(v.z, 0.f); v.w = fmaxf(v.w, 0.f);
                }
                *(float4*)(C + (size_t)gm * N + gn) = v;
            }
        }
    }
}

// ================= small-N SGEMM (64x64 tile) for narrow outputs =================
#define BM 64
#define BN 64
#define BK 16
__global__ __launch_bounds__(256) void sgemm(
    const float* __restrict__ A, const float* __restrict__ B, float* __restrict__ C,
    int M, int N, int K, const float* __restrict__ bias, int do_relu)
{
    __shared__ float As[BK][BM + 1];
    __shared__ float Bs[BK][BN];

    int tid = threadIdx.x;
    int tx = tid & 15;
    int ty = tid >> 4;
    int bm0 = blockIdx.y * BM;
    int bn0 = blockIdx.x * BN;

    float acc[4][4];
    #pragma unroll
    for (int i = 0; i < 4; i++)
        #pragma unroll
        for (int j = 0; j < 4; j++) acc[i][j] = 0.f;

    for (int k0 = 0; k0 < K; k0 += BK) {
        #pragma unroll
        for (int l = 0; l < 4; l++) {
            int idx = tid + l * 256;
            int m = idx >> 4;
            int k = idx & 15;
            int gm = bm0 + m, gk = k0 + k;
            As[k][m] = (gm < M && gk < K) ? A[(size_t)gm * K + gk] : 0.f;
        }
        #pragma unroll
        for (int l = 0; l < 4; l++) {
            int idx = tid + l * 256;
            int k = idx >> 6;
            int n = idx & 63;
            int gk = k0 + k, gn = bn0 + n;
            Bs[k][n] = (gk < K && gn < N) ? B[(size_t)gk * N + gn] : 0.f;
        }
        __syncthreads();

        #pragma unroll
        for (int k = 0; k < BK; k++) {
            float ra[4], rb[4];
            #pragma unroll
            for (int i = 0; i < 4; i++) ra[i] = As[k][ty * 4 + i];
            #pragma unroll
            for (int j = 0; j < 4; j++) rb[j] = Bs[k][tx * 4 + j];
            #pragma unroll
            for (int i = 0; i < 4; i++)
                #pragma unroll
                for (int j = 0; j < 4; j++) acc[i][j] = fmaf(ra[i], rb[j], acc[i][j]);
        }
        __syncthreads();
    }

    #pragma unroll
    for (int i = 0; i < 4; i++) {
        int gm = bm0 + ty * 4 + i;
        if (gm >= M) continue;
        #pragma unroll
        for (int j = 0; j < 4; j++) {
            int gn = bn0 + tx * 4 + j;
            if (gn >= N) continue;
            float v = acc[i][j];
            if (bias) v += bias[gn];
            if (do_relu) v = fmaxf(v, 0.f);
            C[(size_t)gm * N + gn] = v;
        }
    }
}

// ---------------- edge kernels (warp per edge; edge_index is int32) ----------------
__global__ void edge_l1(const float* __restrict__ ea, const int* __restrict__ ei, int E) {
    int e = blockIdx.x * (blockDim.x >> 5) + (threadIdx.x >> 5);
    if (e >= E) return;
    int lane = threadIdx.x & 31;
    float cv = (lane < E_DIM) ? ea[(size_t)e * E_DIM + lane] : (lane == E_DIM ? 1.f : 0.f);
    int src = ei[e];
    int dst = ei[E + e];
    if ((unsigned)src >= NN || (unsigned)dst >= NN) return;
    const float* q = g_q1 + (size_t)src * Q1W;
    float a0 = 0.f, a1 = 0.f;
    #pragma unroll
    for (int k = 0; k < KX; k++) {
        float ck = __shfl_sync(0xffffffffu, cv, k);
        a0 = fmaf(ck, q[k * H2 + lane], a0);
        a1 = fmaf(ck, q[k * H2 + lane + 32], a1);
    }
    atomicAdd(&g_agg1[(size_t)dst * H2 + lane], a0);
    atomicAdd(&g_agg1[(size_t)dst * H2 + lane + 32], a1);
}

__global__ void edge_l2(const float* __restrict__ ea, const int* __restrict__ ei, int E) {
    int e = blockIdx.x * (blockDim.x >> 5) + (threadIdx.x >> 5);
    if (e >= E) return;
    int lane = threadIdx.x & 31;
    float cv = (lane < E_DIM) ? ea[(size_t)e * E_DIM + lane] : (lane == E_DIM ? 1.f : 0.f);
    int src = ei[e];
    int dst = ei[E + e];
    if ((unsigned)src >= NN || (unsigned)dst >= NN) return;
    const float* q = g_q2 + (size_t)src * Q2W;
    float a = 0.f;
    #pragma unroll
    for (int k = 0; k < KX; k++) {
        float ck = __shfl_sync(0xffffffffu, cv, k);
        if (lane < CC) a = fmaf(ck, q[k * CC + lane], a);
    }
    if (lane < CC) atomicAdd(&g_agg2[(size_t)dst * CC + lane], a);
}

// ---------------- relu + log_softmax ----------------
__global__ void relu_copy(int n) {
    int i = blockIdx.x * blockDim.x + threadIdx.x;
    if (i < n) g_h2[i] = fmaxf(g_agg1[i], 0.f);
}

__global__ void log_softmax_rows(float* __restrict__ out, int n) {
    int r = blockIdx.x * blockDim.x + threadIdx.x;
    if (r >= n) return;
    const float* z = g_agg2 + (size_t)r * CC;
    float m = z[0];
    #pragma unroll
    for (int c = 1; c < CC; c++) m = fmaxf(m, z[c]);
    float s = 0.f;
    #pragma unroll
    for (int c = 0; c < CC; c++) s += __expf(z[c] - m);
    float ls = m + logf(s);
    #pragma unroll
    for (int c = 0; c < CC; c++) out[(size_t)r * CC + c] = z[c] - ls;
}

// ---------------- launch ----------------
extern "C" void kernel_launch(void* const* d_in, const int* in_sizes, int n_in,
                              void* d_out, int out_size)
{
    const float* x     = (const float*)d_in[0];
    const float* ea    = (const float*)d_in[1];
    const int*   ei    = (const int*)d_in[2];
    const float* W1    = (const float*)d_in[3];
    const float* b1    = (const float*)d_in[4];
    const float* We1   = (const float*)d_in[5];
    const float* be1   = (const float*)d_in[6];
    const float* root1 = (const float*)d_in[7];
    const float* bias1 = (const float*)d_in[8];
    const float* We2   = (const float*)d_in[9];
    const float* be2   = (const float*)d_in[10];
    const float* root2 = (const float*)d_in[11];
    const float* bias2 = (const float*)d_in[12];
    float* out = (float*)d_out;

    int N = in_sizes[0] / D_IN;
    int E = in_sizes[2] / 2;

    float *p_h1, *p_q1, *p_agg1, *p_h2, *p_q2, *p_M1, *p_M2, *p_agg2;
    cudaGetSymbolAddress((void**)&p_h1,   g_h1);
    cudaGetSymbolAddress((void**)&p_q1,   g_q1);
    cudaGetSymbolAddress((void**)&p_agg1, g_agg1);
    cudaGetSymbolAddress((void**)&p_h2,   g_h2);
    cudaGetSymbolAddress((void**)&p_q2,   g_q2);
    cudaGetSymbolAddress((void**)&p_M1,   g_M1);
    cudaGetSymbolAddress((void**)&p_M2,   g_M2);
    cudaGetSymbolAddress((void**)&p_agg2, g_agg2);

    dim3 blk(256);

    pack_m1<<<(H1 * Q1W + 255) / 256, blk>>>(We1, be1);
    pack_m2<<<(H2 * Q2W + 255) / 256, blk>>>(We2, be2);

    // h1 = relu(x @ W1 + b1)            [N,64]@[64,128]  (K=64%8 ok, N=128%4 ok)
    {
        dim3 g((H1 + GN - 1) / GN, (N + GM - 1) / GM);
        sgemm128<<<g, blk>>>(x, W1, p_h1, N, H1, D_IN, b1, 1);
    }
    // q1 = h1 @ M1                      [N,128]@[128,1088]   (dominant GEMM)
    {
        dim3 g((Q1W + GN - 1) / GN, (N + GM - 1) / GM);
        sgemm128<<<g, blk>>>(p_h1, p_M1, p_q1, N, Q1W, H1, nullptr, 0);
    }
    // agg1 = h1 @ root1 + bias1         [N,128]@[128,64]
    {
        dim3 g((H2 + BN - 1) / BN, (N + BM - 1) / BM);
        sgemm<<<g, blk>>>(p_h1, root1, p_agg1, N, H2, H1, bias1, 0);
    }
    edge_l1<<<(E + 3) / 4, 128>>>(ea, ei, E);
    relu_copy<<<(N * H2 + 255) / 256, blk>>>(N * H2);
    // q2 = h2 @ M2                      [N,64]@[64,170]
    {
        dim3 g((Q2W + BN - 1) / BN, (N + BM - 1) / BM);
        sgemm<<<g, blk>>>(p_h2, p_M2, p_q2, N, Q2W, H2, nullptr, 0);
    }
    // agg2 = h2 @ root2 + bias2         [N,64]@[64,10]
    {
        dim3 g((CC + BN - 1) / BN, (N + BM - 1) / BM);
        sgemm<<<g, blk>>>(p_h2, root2, p_agg2, N, CC, H2, bias2, 0);
    }
    edge_l2<<<(E + 3) / 4, 128>>>(ea, ei, E);
    log_softmax_rows<<<(N + 255) / 256, blk>>>(out, N);
}